// round 4
// baseline (speedup 1.0000x reference)
#include <cuda_runtime.h>
#include <cstdint>

#define HORIZON 20
#define DT      0.1f
#define DT2     0.01f
#define EPSV    1e-4f
#define V_MAX   0.22f
#define W_MAX   2.8f

typedef unsigned long long u64;

// ---------------- packed f32x2 helpers (sm_100+ PTX) ----------------
__device__ __forceinline__ u64 pk2(float lo, float hi) {
    u64 d; asm("mov.b64 %0, {%1, %2};" : "=l"(d) : "f"(lo), "f"(hi)); return d;
}
__device__ __forceinline__ void unpk2(u64 d, float& lo, float& hi) {
    asm("mov.b64 {%0, %1}, %2;" : "=f"(lo), "=f"(hi) : "l"(d));
}
__device__ __forceinline__ u64 fma2(u64 a, u64 b, u64 c) {
    u64 d; asm("fma.rn.f32x2 %0, %1, %2, %3;" : "=l"(d) : "l"(a), "l"(b), "l"(c)); return d;
}
__device__ __forceinline__ u64 mul2(u64 a, u64 b) {
    u64 d; asm("mul.rn.f32x2 %0, %1, %2;" : "=l"(d) : "l"(a), "l"(b)); return d;
}
__device__ __forceinline__ u64 add2(u64 a, u64 b) {
    u64 d; asm("add.rn.f32x2 %0, %1, %2;" : "=l"(d) : "l"(a), "l"(b)); return d;
}
__device__ __forceinline__ u64 neg2(u64 a) { return a ^ 0x8000000080000000ULL; }

// rcp.approx per lane + one packed Newton-Raphson step -> ~1 ulp fp32
__device__ __forceinline__ u64 rcp2(u64 d, u64 two) {
    float lo, hi, rl, rh;
    unpk2(d, lo, hi);
    asm("rcp.approx.ftz.f32 %0, %1;" : "=f"(rl) : "f"(lo));
    asm("rcp.approx.ftz.f32 %0, %1;" : "=f"(rh) : "f"(hi));
    u64 x = pk2(rl, rh);
    u64 e = fma2(neg2(d), x, two);   // 2 - d*x
    return mul2(x, e);
}

// ---------------- weights (batch-invariant) ----------------
// layout: q0,q1,q2, r0+2eps, r1+2eps, qf0,qf1,qf2
__device__ float g_par[8];

__device__ __forceinline__ float softplus_f(float x) {
    return fmaxf(x, 0.0f) + log1pf(expf(-fabsf(x)));
}

__global__ void prep_kernel(const float* __restrict__ q_raw,
                            const float* __restrict__ r_raw,
                            const float* __restrict__ qf_raw) {
    if (threadIdx.x == 0 && blockIdx.x == 0) {
        g_par[0] = softplus_f(q_raw[0]) + EPSV;
        g_par[1] = softplus_f(q_raw[1]) + EPSV;
        g_par[2] = softplus_f(q_raw[2]) + EPSV;
        // r includes +eps from softplus path AND +eps on S's diagonal: fold both
        g_par[3] = softplus_f(r_raw[0]) + EPSV + EPSV;
        g_par[4] = softplus_f(r_raw[1]) + EPSV + EPSV;
        g_par[5] = softplus_f(qf_raw[0]) + EPSV;
        g_par[6] = softplus_f(qf_raw[1]) + EPSV;
        g_par[7] = softplus_f(qf_raw[2]) + EPSV;
    }
}

// ---------------- main kernel: 2 batch elements per thread ----------------
__global__ void __launch_bounds__(256)
lqr_kernel(const float* __restrict__ ref, float4* __restrict__ out, int npairs) {
    int t = blockIdx.x * 256 + threadIdx.x;
    if (t >= npairs) return;

    // load two 5-float rows
    const float* p = ref + (size_t)t * 10;
    float e0x = __ldg(p + 0), e0y = __ldg(p + 1), e0h = __ldg(p + 2);
    float v0  = __ldg(p + 3), w0  = __ldg(p + 4);
    float e1x = __ldg(p + 5), e1y = __ldg(p + 6), e1h = __ldg(p + 7);
    float v1  = __ldg(p + 8), w1  = __ldg(p + 9);

    u64 ex = pk2(e0x, e1x), ey = pk2(e0y, e1y), eh = pk2(e0h, e1h);
    u64 vr = pk2(v0, v1),   wr = pk2(w0, w1);

    // scalar model params (broadcast loads, L1/L2-cached)
    float q0 = g_par[0], q1 = g_par[1], q2 = g_par[2];
    float r0 = g_par[3], r1 = g_par[4];
    float f0 = g_par[5], f1 = g_par[6], f2 = g_par[7];

    u64 q0p = pk2(q0, q0), q1p = pk2(q1, q1), q2p = pk2(q2, q2);
    u64 r0e = pk2(r0, r0), r1e = pk2(r1, r1);
    u64 DT2p = pk2(DT2, DT2);
    u64 DTp  = pk2(DT, DT);
    u64 TWO  = pk2(2.0f, 2.0f);

    // a = dt*w, b = dt*v   (A = [[1,a,0],[-a,1,b],[0,0,1]])
    u64 aa = mul2(DTp, wr);
    u64 bb = mul2(DTp, vr);
    u64 na = neg2(aa);

    // symmetric P, init diag(qf)
    u64 p00 = pk2(f0, f0), p11 = pk2(f1, f1), p22 = pk2(f2, f2);
    u64 p01 = pk2(0.f, 0.f), p02 = p01, p12 = p01;

    // 19 full Riccati updates (the 20th step only produces K0)
    #pragma unroll 1
    for (int it = 0; it < HORIZON - 1; ++it) {
        // S = R + dt^2 [[p00,p02],[p02,p22]] + eps I   (eps folded into r0e/r1e)
        u64 S00 = fma2(DT2p, p00, r0e);
        u64 S01 = mul2(DT2p, p02);
        u64 S11 = fma2(DT2p, p22, r1e);
        u64 nS01 = neg2(S01);
        u64 det = fma2(nS01, S01, mul2(S00, S11));
        u64 inv = rcp2(det, TWO);
        // T = dt^2 * invdet * adj(S)
        u64 tt  = mul2(DT2p, inv);
        u64 T00 = mul2(tt, S11);
        u64 T01 = mul2(tt, nS01);
        u64 T11 = mul2(tt, S00);
        // M' rows = rows 0 and 2 of P*A
        u64 m00 = fma2(na, p01, p00);
        u64 m01 = fma2(aa, p00, p01);
        u64 m02 = fma2(bb, p01, p02);
        u64 m10 = fma2(na, p12, p02);
        u64 m11 = fma2(aa, p02, p12);
        u64 m12 = fma2(bb, p12, p22);
        // row 1 of P*A
        u64 C10 = fma2(na, p11, p01);
        u64 C11 = fma2(aa, p01, p11);
        u64 C12 = fma2(bb, p11, p12);
        // G = A^T (P A), symmetric part
        u64 G00 = fma2(na, C10, m00);
        u64 G01 = fma2(na, C11, m01);
        u64 G02 = fma2(na, C12, m02);
        u64 G11 = fma2(aa, m01, C11);
        u64 G12 = fma2(aa, m02, C12);
        u64 G22 = fma2(bb, C12, m12);
        // L = T * M'
        u64 L00 = fma2(T01, m10, mul2(T00, m00));
        u64 L01 = fma2(T01, m11, mul2(T00, m01));
        u64 L02 = fma2(T01, m12, mul2(T00, m02));
        u64 L10 = fma2(T11, m10, mul2(T01, m00));
        u64 L11 = fma2(T11, m11, mul2(T01, m01));
        u64 L12 = fma2(T11, m12, mul2(T01, m02));
        u64 nL00 = neg2(L00), nL01 = neg2(L01), nL02 = neg2(L02);
        u64 nL10 = neg2(L10), nL11 = neg2(L11), nL12 = neg2(L12);
        // P_new = Qdiag + G - M'^T L
        p00 = fma2(m10, nL10, fma2(m00, nL00, add2(G00, q0p)));
        p01 = fma2(m10, nL11, fma2(m00, nL01, G01));
        p02 = fma2(m10, nL12, fma2(m00, nL02, G02));
        p11 = fma2(m11, nL11, fma2(m01, nL01, add2(G11, q1p)));
        p12 = fma2(m11, nL12, fma2(m01, nL02, G12));
        p22 = fma2(m12, nL12, fma2(m02, nL02, add2(G22, q2p)));
    }

    // 20th step: only the gain. delta_u = -K e = +dt*invdet * adj(S) @ (M' e)
    u64 S00 = fma2(DT2p, p00, r0e);
    u64 S01 = mul2(DT2p, p02);
    u64 S11 = fma2(DT2p, p22, r1e);
    u64 nS01 = neg2(S01);
    u64 det = fma2(nS01, S01, mul2(S00, S11));
    u64 inv = rcp2(det, TWO);

    u64 m00 = fma2(na, p01, p00);
    u64 m01 = fma2(aa, p00, p01);
    u64 m02 = fma2(bb, p01, p02);
    u64 m10 = fma2(na, p12, p02);
    u64 m11 = fma2(aa, p02, p12);
    u64 m12 = fma2(bb, p12, p22);

    u64 me0 = fma2(m02, eh, fma2(m01, ey, mul2(m00, ex)));
    u64 me1 = fma2(m12, eh, fma2(m11, ey, mul2(m10, ex)));

    u64 g0 = fma2(nS01, me1, mul2(S11, me0));   // adj(S) @ me, row 0
    u64 g1 = fma2(S00, me1, mul2(nS01, me0));   // row 1
    u64 sp = mul2(inv, DTp);                    // dt * invdet

    u64 u0 = fma2(sp, g0, vr);                  // u_ref + delta_u
    u64 u1 = fma2(sp, g1, wr);

    float uv0, uv1, uw0, uw1;
    unpk2(u0, uv0, uv1);
    unpk2(u1, uw0, uw1);
    uv0 = fminf(fmaxf(uv0, -V_MAX), V_MAX);
    uv1 = fminf(fmaxf(uv1, -V_MAX), V_MAX);
    uw0 = fminf(fmaxf(uw0, -W_MAX), W_MAX);
    uw1 = fminf(fmaxf(uw1, -W_MAX), W_MAX);

    out[t] = make_float4(uv0, uw0, uv1, uw1);
}

extern "C" void kernel_launch(void* const* d_in, const int* in_sizes, int n_in,
                              void* d_out, int out_size) {
    const float* ref    = (const float*)d_in[0];
    const float* q_raw  = (const float*)d_in[1];
    const float* r_raw  = (const float*)d_in[2];
    const float* qf_raw = (const float*)d_in[3];

    int batch  = in_sizes[0] / 5;
    int npairs = batch / 2;
    int grid   = (npairs + 255) / 256;

    prep_kernel<<<1, 32>>>(q_raw, r_raw, qf_raw);
    lqr_kernel<<<grid, 256>>>(ref, (float4*)d_out, npairs);
}

// round 6
// speedup vs baseline: 1.1472x; 1.1472x over previous
#include <cuda_runtime.h>
#include <cstdint>

#define HORIZON 20
#define DT      0.1f
#define DT2     (DT*DT)
#define INV_DT  10.0f
#define EPSV    1e-4f
#define V_MAX   0.22f
#define W_MAX   2.8f

typedef unsigned long long u64;

// ---------------- packed f32x2 helpers (sm_100+ PTX) ----------------
__device__ __forceinline__ u64 pk2(float lo, float hi) {
    u64 d; asm("mov.b64 %0, {%1, %2};" : "=l"(d) : "f"(lo), "f"(hi)); return d;
}
__device__ __forceinline__ void unpk2(u64 d, float& lo, float& hi) {
    asm("mov.b64 {%0, %1}, %2;" : "=f"(lo), "=f"(hi) : "l"(d));
}
__device__ __forceinline__ u64 fma2(u64 a, u64 b, u64 c) {
    u64 d; asm("fma.rn.f32x2 %0, %1, %2, %3;" : "=l"(d) : "l"(a), "l"(b), "l"(c)); return d;
}
__device__ __forceinline__ u64 mul2(u64 a, u64 b) {
    u64 d; asm("mul.rn.f32x2 %0, %1, %2;" : "=l"(d) : "l"(a), "l"(b)); return d;
}
__device__ __forceinline__ u64 add2(u64 a, u64 b) {
    u64 d; asm("add.rn.f32x2 %0, %1, %2;" : "=l"(d) : "l"(a), "l"(b)); return d;
}
__device__ __forceinline__ u64 neg2(u64 a) { return a ^ 0x8000000080000000ULL; }

// rcp.approx per lane + one packed Newton-Raphson step -> ~1 ulp fp32
__device__ __forceinline__ u64 rcp2(u64 d, u64 two) {
    float lo, hi, rl, rh;
    unpk2(d, lo, hi);
    asm("rcp.approx.ftz.f32 %0, %1;" : "=f"(rl) : "f"(lo));
    asm("rcp.approx.ftz.f32 %0, %1;" : "=f"(rh) : "f"(hi));
    u64 x = pk2(rl, rh);
    u64 e = fma2(neg2(d), x, two);   // 2 - d*x
    return mul2(x, e);
}

// ---------------- weights (batch-invariant) ----------------
// layout: dt^2*q0, dt^2*q1, dt^2*q2, r0+2eps, r1+2eps, dt^2*qf0, dt^2*qf1, dt^2*qf2
__device__ float g_par[8];

__device__ __forceinline__ float softplus_f(float x) {
    return fmaxf(x, 0.0f) + log1pf(expf(-fabsf(x)));
}

__global__ void prep_kernel(const float* __restrict__ q_raw,
                            const float* __restrict__ r_raw,
                            const float* __restrict__ qf_raw) {
    if (threadIdx.x == 0 && blockIdx.x == 0) {
        g_par[0] = DT2 * (softplus_f(q_raw[0]) + EPSV);
        g_par[1] = DT2 * (softplus_f(q_raw[1]) + EPSV);
        g_par[2] = DT2 * (softplus_f(q_raw[2]) + EPSV);
        // r includes +eps from softplus path AND +eps on S's diagonal
        g_par[3] = softplus_f(r_raw[0]) + EPSV + EPSV;
        g_par[4] = softplus_f(r_raw[1]) + EPSV + EPSV;
        g_par[5] = DT2 * (softplus_f(qf_raw[0]) + EPSV);
        g_par[6] = DT2 * (softplus_f(qf_raw[1]) + EPSV);
        g_par[7] = DT2 * (softplus_f(qf_raw[2]) + EPSV);
    }
}

// ---------------- main kernel: 2 batch elements per thread ----------------
// Works in scaled space P~ = dt^2 * P:
//   S   = [r0' + p00, p02; p02, r1' + p22]   (S01 = p02, no multiply)
//   P~' = Q~ + A^T P~ A - M~^T (inv(det) adj(S)) M~,  M~ = rows {0,2} of P~ A
__global__ void __launch_bounds__(128, 9)
lqr_kernel(const float* __restrict__ ref, float4* __restrict__ out, int npairs) {
    int t = blockIdx.x * 128 + threadIdx.x;
    if (t >= npairs) return;

    const float* p = ref + (size_t)t * 10;
    float v0 = __ldg(p + 3), w0 = __ldg(p + 4);
    float v1 = __ldg(p + 8), w1 = __ldg(p + 9);

    u64 vr = pk2(v0, v1), wr = pk2(w0, w1);

    float q0 = g_par[0], q1 = g_par[1], q2 = g_par[2];
    float r0 = g_par[3], r1 = g_par[4];
    float f0 = g_par[5], f1 = g_par[6], f2 = g_par[7];

    u64 q0p = pk2(q0, q0), q1p = pk2(q1, q1), q2p = pk2(q2, q2);
    u64 r0e = pk2(r0, r0), r1e = pk2(r1, r1);
    u64 TWO = pk2(2.0f, 2.0f);
    u64 DTp = pk2(DT, DT);

    // a = dt*w, b = dt*v   (A = [[1,a,0],[-a,1,b],[0,0,1]])
    u64 aa = mul2(DTp, wr);
    u64 bb = mul2(DTp, vr);
    u64 na = neg2(aa);

    // scaled symmetric P~, init dt^2 * diag(qf)
    u64 p00 = pk2(f0, f0), p11 = pk2(f1, f1), p22 = pk2(f2, f2);
    u64 p01 = pk2(0.f, 0.f), p02 = p01, p12 = p01;

    // 19 full Riccati updates (the 20th step only produces the gain)
    #pragma unroll 1
    for (int it = 0; it < HORIZON - 1; ++it) {
        // S (S01 = p02 directly)
        u64 S00 = add2(p00, r0e);
        u64 S11 = add2(p22, r1e);
        u64 np02 = neg2(p02);
        u64 det = fma2(np02, p02, mul2(S00, S11));
        u64 inv = rcp2(det, TWO);
        u64 ninv = neg2(inv);
        // T' chosen so L' = T'-combination = -(inv adj(S)) M~
        u64 T00 = mul2(ninv, S11);
        u64 T01 = mul2(inv, p02);
        u64 T11 = mul2(ninv, S00);
        // M~ rows = rows 0 and 2 of P~ A
        u64 m00 = fma2(na, p01, p00);
        u64 m01 = fma2(aa, p00, p01);
        u64 m02 = fma2(bb, p01, p02);
        u64 m10 = fma2(na, p12, p02);
        u64 m11 = fma2(aa, p02, p12);
        u64 m12 = fma2(bb, p12, p22);
        // row 1 of P~ A
        u64 C10 = fma2(na, p11, p01);
        u64 C11 = fma2(aa, p01, p11);
        u64 C12 = fma2(bb, p11, p12);
        // G = A^T (P~ A), symmetric part
        u64 G00 = fma2(na, C10, m00);
        u64 G01 = fma2(na, C11, m01);
        u64 G02 = fma2(na, C12, m02);
        u64 G11 = fma2(aa, m01, C11);
        u64 G12 = fma2(aa, m02, C12);
        u64 G22 = fma2(bb, C12, m12);
        // L' = -(inv adj(S)) M~   (already sign-flipped via T')
        u64 L00 = fma2(T01, m10, mul2(T00, m00));
        u64 L01 = fma2(T01, m11, mul2(T00, m01));
        u64 L02 = fma2(T01, m12, mul2(T00, m02));
        u64 L10 = fma2(T11, m10, mul2(T01, m00));
        u64 L11 = fma2(T11, m11, mul2(T01, m01));
        u64 L12 = fma2(T11, m12, mul2(T01, m02));
        // P~_new = Q~ + G + M~^T L'
        p00 = fma2(m10, L10, fma2(m00, L00, add2(G00, q0p)));
        p01 = fma2(m10, L11, fma2(m00, L01, G01));
        p02 = fma2(m10, L12, fma2(m00, L02, G02));
        p11 = fma2(m11, L11, fma2(m01, L01, add2(G11, q1p)));
        p12 = fma2(m11, L12, fma2(m01, L02, G12));
        p22 = fma2(m12, L12, fma2(m02, L02, add2(G22, q2p)));
    }

    // 20th step: only the gain.
    // delta_u = dt * invdet * adj(S) @ (M e)  with M = M~/dt^2
    //         = (inv/dt) * adj(S) @ (M~ e)
    u64 S00 = add2(p00, r0e);
    u64 S11 = add2(p22, r1e);
    u64 np02 = neg2(p02);
    u64 det = fma2(np02, p02, mul2(S00, S11));
    u64 inv = rcp2(det, TWO);

    u64 m00 = fma2(na, p01, p00);
    u64 m01 = fma2(aa, p00, p01);
    u64 m02 = fma2(bb, p01, p02);
    u64 m10 = fma2(na, p12, p02);
    u64 m11 = fma2(aa, p02, p12);
    u64 m12 = fma2(bb, p12, p22);

    // reload errors (L2-resident)
    float e0x = __ldg(p + 0), e0y = __ldg(p + 1), e0h = __ldg(p + 2);
    float e1x = __ldg(p + 5), e1y = __ldg(p + 6), e1h = __ldg(p + 7);
    u64 ex = pk2(e0x, e1x), ey = pk2(e0y, e1y), eh = pk2(e0h, e1h);

    u64 me0 = fma2(m02, eh, fma2(m01, ey, mul2(m00, ex)));
    u64 me1 = fma2(m12, eh, fma2(m11, ey, mul2(m10, ex)));

    u64 g0 = fma2(np02, me1, mul2(S11, me0));   // adj(S) @ me, row 0
    u64 g1 = fma2(S00, me1, mul2(np02, me0));   // row 1

    u64 TEN = pk2(INV_DT, INV_DT);
    u64 sp = mul2(inv, TEN);                    // inv / dt

    // u_ref reconstructed from aa/bb (v = b/dt, w = a/dt)
    u64 vrr = mul2(bb, TEN);
    u64 wrr = mul2(aa, TEN);
    u64 u0 = fma2(sp, g0, vrr);
    u64 u1 = fma2(sp, g1, wrr);

    float uv0, uv1, uw0, uw1;
    unpk2(u0, uv0, uv1);
    unpk2(u1, uw0, uw1);
    uv0 = fminf(fmaxf(uv0, -V_MAX), V_MAX);
    uv1 = fminf(fmaxf(uv1, -V_MAX), V_MAX);
    uw0 = fminf(fmaxf(uw0, -W_MAX), W_MAX);
    uw1 = fminf(fmaxf(uw1, -W_MAX), W_MAX);

    out[t] = make_float4(uv0, uw0, uv1, uw1);
}

extern "C" void kernel_launch(void* const* d_in, const int* in_sizes, int n_in,
                              void* d_out, int out_size) {
    const float* ref    = (const float*)d_in[0];
    const float* q_raw  = (const float*)d_in[1];
    const float* r_raw  = (const float*)d_in[2];
    const float* qf_raw = (const float*)d_in[3];

    int batch  = in_sizes[0] / 5;
    int npairs = batch / 2;
    int grid   = (npairs + 127) / 128;

    prep_kernel<<<1, 32>>>(q_raw, r_raw, qf_raw);
    lqr_kernel<<<grid, 128>>>(ref, (float4*)d_out, npairs);
}